// round 5
// baseline (speedup 1.0000x reference)
#include <cuda_runtime.h>
#include <cuda_bf16.h>
#include <math.h>
#include <stdint.h>

// ---------------------------------------------------------------------------
// Problem constants (B=4, C=128, H=W=128, NH=8, d=16, GDFN hidden=512)
// ---------------------------------------------------------------------------
#define BATCH 4
#define CH    128
#define HW    16384
#define NHEAD 8
#define DHEAD 16
#define ALOG_SEGS 128

// ---------------------------------------------------------------------------
// Scratch (device globals)
// ---------------------------------------------------------------------------
__device__ float g_bufA[BATCH * 512 * HW];
__device__ float g_bufB[BATCH * 512 * HW];
__device__ float g_partS [32 * ALOG_SEGS * 256];
__device__ float g_partQ2[32 * ALOG_SEGS * 16];
__device__ float g_partK2[32 * ALOG_SEGS * 16];
__device__ float g_attn  [32 * 256];
__device__ uint32_t g_WqP  [384 * 128];      // packed tf32 fragments (qkv, ln1-scaled)
__device__ uint32_t g_Wg1P [512 * 128];      // packed tf32 fragments (g1, ln2-scaled)
__device__ uint32_t g_Wg2P [128 * 256];      // packed tf32 fragments (g2)
__device__ uint32_t g_WeffP[BATCH * 128 * 128];  // packed per-batch proj*attn
__device__ float g_rs[896];
__device__ float g_cb[896];

// ---------------------------------------------------------------------------
// helpers
// ---------------------------------------------------------------------------
__device__ __forceinline__ uint32_t f2tf(float v)
{
    uint32_t r;
    asm("cvt.rna.tf32.f32 %0, %1;" : "=r"(r) : "f"(v));
    return r;
}

__device__ __forceinline__ void mma_tf32(float* d, const uint32_t* a, const uint32_t* b)
{
    asm volatile(
        "mma.sync.aligned.m16n8k8.row.col.f32.tf32.tf32.f32 "
        "{%0,%1,%2,%3},{%4,%5,%6,%7},{%8,%9},{%0,%1,%2,%3};"
        : "+f"(d[0]), "+f"(d[1]), "+f"(d[2]), "+f"(d[3])
        : "r"(a[0]), "r"(a[1]), "r"(a[2]), "r"(a[3]), "r"(b[0]), "r"(b[1]));
}

__device__ __forceinline__ float gelu_exact(float v)
{
    return 0.5f * v * (1.f + erff(v * 0.70710678118654752440f));
}

// Fragment-major pack index for mma.m16n8k8 A operand.
// reg order: a0=[r][c] a1=[r+8][c] a2=[r][c+4] a3=[r+8][c+4]
__device__ __forceinline__ int packA(int oc, int k, int K)
{
    int by = oc >> 7, ocl = oc & 127;
    int wm = ocl >> 6, mt = (ocl >> 4) & 3, pair = (ocl >> 3) & 1, gid = ocl & 7;
    int s  = k >> 4,  ks = (k >> 3) & 1,  ch   = (k >> 2) & 1,  tig = k & 3;
    int lane = gid * 4 + tig;
    int u    = mt * 2 + ks;
    int reg  = ch * 2 + pair;
    return (((by * (K >> 4) + s) * 2 + wm) * 8 + u) * 128 + lane * 4 + reg;
}

// ---------------------------------------------------------------------------
// 0) Weight prep: scale by LN weight, compute rowsum/cbias, pack tf32 frags.
//    warp per row: rows 0..383 qkv | 384..895 g1 | 896..1023 g2
// ---------------------------------------------------------------------------
__global__ __launch_bounds__(256) void prep_w_k(const float* __restrict__ qkv_pw,
                                                const float* __restrict__ ln1w,
                                                const float* __restrict__ ln1b,
                                                const float* __restrict__ g1w,
                                                const float* __restrict__ ln2w,
                                                const float* __restrict__ ln2b,
                                                const float* __restrict__ g2w)
{
    int row  = blockIdx.x * 8 + (threadIdx.x >> 5);
    int lane = threadIdx.x & 31;

    if (row < 896) {
        const float *W, *lw, *lb;
        uint32_t* Wp;
        int rl;
        if (row < 384) { W = qkv_pw + (size_t)row * 128; lw = ln1w; lb = ln1b; Wp = g_WqP;  rl = row; }
        else           { W = g1w + (size_t)(row - 384) * 128; lw = ln2w; lb = ln2b; Wp = g_Wg1P; rl = row - 384; }
        float rs = 0.f, cb = 0.f;
#pragma unroll
        for (int t = 0; t < 4; t++) {
            int c = lane + t * 32;
            float w = W[c];
            float wp = w * lw[c];
            Wp[packA(rl, c, 128)] = f2tf(wp);
            rs += wp;
            cb += w * lb[c];
        }
#pragma unroll
        for (int o = 16; o > 0; o >>= 1) {
            rs += __shfl_xor_sync(0xffffffffu, rs, o);
            cb += __shfl_xor_sync(0xffffffffu, cb, o);
        }
        if (lane == 0) { g_rs[row] = rs; g_cb[row] = cb; }
    } else {
        int r = row - 896;
#pragma unroll
        for (int t = 0; t < 8; t++) {
            int c = lane + t * 32;
            g_Wg2P[packA(r, c, 256)] = f2tf(g2w[r * 256 + c]);
        }
    }
}

// ---------------------------------------------------------------------------
// 1) tf32 GEMM, A from packed-fragment global (L1/L2 resident), B via smem.
//    MODE 0: plain   MODE 1: LN-in-epilogue   MODE 2: gelu-gate-on-load
// ---------------------------------------------------------------------------
#define BM  128
#define BN  128
#define BK  16
#define BNP 136

template <int MODE, bool RESID>
__global__ __launch_bounds__(256) void gemm_tc(
    const uint32_t* __restrict__ Ap,  // packed tf32 fragments
    const float* __restrict__ X,      // (B, XCH, HW)
    const float* __restrict__ rsum,
    const float* __restrict__ cbias,
    const float* __restrict__ resid,
    float* __restrict__ out,          // (B, OC, HW)
    int OC, int K, int XCH, int wbstride)
{
    __shared__ uint32_t Xs[2][BK * BNP];

    const int b    = blockIdx.z;
    const int n0   = blockIdx.x * BN;
    const int oc0  = blockIdx.y * BM;
    const int tid  = threadIdx.x;
    const int warp = tid >> 5;
    const int lane = tid & 31;
    const int wm   = warp >> 2;
    const int wn   = warp & 3;
    const int gid  = lane >> 2;
    const int tig  = lane & 3;

    const int nstages = K >> 4;
    const int byNS    = blockIdx.y * nstages;

    const uint4* Abase = (const uint4*)(Ap + (size_t)b * wbstride) + wm * 256 + lane;
    const float* Xb = X + (size_t)b * XCH * HW;

    float acc[4][4][4];
#pragma unroll
    for (int mt = 0; mt < 4; mt++)
#pragma unroll
        for (int nt = 0; nt < 4; nt++)
#pragma unroll
            for (int r = 0; r < 4; r++) acc[mt][nt][r] = 0.f;

    float cs[4]  = {0.f, 0.f, 0.f, 0.f};
    float cs2[4] = {0.f, 0.f, 0.f, 0.f};

    float4 xreg[2];

    auto load_x = [&](int k0) {
#pragma unroll
        for (int t = 0; t < 2; t++) {
            int idx = tid + t * 256;
            int kk = idx >> 5, n4 = (idx & 31) << 2;
            int kg = k0 + kk;
            int n  = n0 + n4;
            if (MODE == 2) {
                float4 v1 = *(const float4*)&Xb[(size_t)kg * HW + n];
                float4 v2 = *(const float4*)&Xb[(size_t)(kg + 256) * HW + n];
                xreg[t].x = gelu_exact(v1.x) * v2.x;
                xreg[t].y = gelu_exact(v1.y) * v2.y;
                xreg[t].z = gelu_exact(v1.z) * v2.z;
                xreg[t].w = gelu_exact(v1.w) * v2.w;
            } else {
                xreg[t] = *(const float4*)&Xb[(size_t)kg * HW + n];
                if (MODE == 1) {
                    cs[0] += xreg[t].x; cs2[0] = fmaf(xreg[t].x, xreg[t].x, cs2[0]);
                    cs[1] += xreg[t].y; cs2[1] = fmaf(xreg[t].y, xreg[t].y, cs2[1]);
                    cs[2] += xreg[t].z; cs2[2] = fmaf(xreg[t].z, xreg[t].z, cs2[2]);
                    cs[3] += xreg[t].w; cs2[3] = fmaf(xreg[t].w, xreg[t].w, cs2[3]);
                }
            }
        }
    };

    auto store_x = [&](int buf) {
#pragma unroll
        for (int t = 0; t < 2; t++) {
            int idx = tid + t * 256;
            int kk = idx >> 5, n4 = (idx & 31) << 2;
            uint32_t* p = &Xs[buf][kk * BNP + n4];
            p[0] = f2tf(xreg[t].x); p[1] = f2tf(xreg[t].y);
            p[2] = f2tf(xreg[t].z); p[3] = f2tf(xreg[t].w);
        }
    };

    load_x(0);
    store_x(0);
    __syncthreads();

    for (int s = 0; s < nstages; s++) {
        int buf = s & 1;

        // A fragments for this stage: 8 coalesced LDG.128 (L1/L2 resident)
        uint4 a4[8];
        {
            const uint4* ap = Abase + (size_t)(byNS + s) * 512;
#pragma unroll
            for (int u = 0; u < 8; u++) a4[u] = ap[u * 32];
        }

        if (s + 1 < nstages) load_x((s + 1) * BK);

#pragma unroll
        for (int ks = 0; ks < 2; ks++) {
            uint32_t bfr[4][2];
#pragma unroll
            for (int nt = 0; nt < 4; nt++) {
                int col = wn * 32 + nt * 8 + gid;
                bfr[nt][0] = Xs[buf][(ks * 8 + tig) * BNP + col];
                bfr[nt][1] = Xs[buf][(ks * 8 + tig + 4) * BNP + col];
            }
#pragma unroll
            for (int mt = 0; mt < 4; mt++)
#pragma unroll
                for (int nt = 0; nt < 4; nt++)
                    mma_tf32(acc[mt][nt], (const uint32_t*)&a4[mt * 2 + ks], bfr[nt]);
        }
        __syncthreads();
        if (s + 1 < nstages) {
            store_x(buf ^ 1);
            __syncthreads();
        }
    }

    // --- MODE 1: per-column LN stats reduction (overlay dead smem) ---
    float* redS  = (float*)&Xs[0][0];        // [8][128]
    float* redS2 = redS + 8 * 128;           // [8][128]
    float* muS   = redS2 + 8 * 128;          // [128]
    float* rsS   = muS + 128;                // [128]   (total 9K < 17.4K)
    if (MODE == 1) {
        int jrow = tid >> 5;
        int nc   = (tid & 31) << 2;
#pragma unroll
        for (int c = 0; c < 4; c++) {
            redS [jrow * 128 + nc + c] = cs[c];
            redS2[jrow * 128 + nc + c] = cs2[c];
        }
        __syncthreads();
        if (tid < 128) {
            float s = 0.f, s2 = 0.f;
#pragma unroll
            for (int j = 0; j < 8; j++) {
                s  += redS [j * 128 + tid];
                s2 += redS2[j * 128 + tid];
            }
            float m   = s * (1.f / 128.f);
            float var = s2 * (1.f / 128.f) - m * m;
            muS[tid] = m;
            rsS[tid] = rsqrtf(var + 1e-5f);
        }
        __syncthreads();
    }

    // --- epilogue ---
#pragma unroll
    for (int mt = 0; mt < 4; mt++) {
        int ocl0 = wm * 64 + mt * 16 + gid;
        float rs0 = 0.f, rs1 = 0.f, cb0 = 0.f, cb1 = 0.f;
        if (MODE == 1) {
            rs0 = rsum[oc0 + ocl0];  rs1 = rsum[oc0 + ocl0 + 8];
            cb0 = cbias[oc0 + ocl0]; cb1 = cbias[oc0 + ocl0 + 8];
        }
#pragma unroll
        for (int nt = 0; nt < 4; nt++) {
            int nl = wn * 32 + nt * 8 + tig * 2;
            size_t base0 = ((size_t)b * OC + oc0 + ocl0) * HW + n0 + nl;
            size_t base1 = ((size_t)b * OC + oc0 + ocl0 + 8) * HW + n0 + nl;
            float2 r0 = make_float2(acc[mt][nt][0], acc[mt][nt][1]);
            float2 r1 = make_float2(acc[mt][nt][2], acc[mt][nt][3]);
            if (MODE == 1) {
                float mu0 = muS[nl], mu1 = muS[nl + 1];
                float rd0 = rsS[nl], rd1 = rsS[nl + 1];
                r0.x = rd0 * (r0.x - mu0 * rs0) + cb0;
                r0.y = rd1 * (r0.y - mu1 * rs0) + cb0;
                r1.x = rd0 * (r1.x - mu0 * rs1) + cb1;
                r1.y = rd1 * (r1.y - mu1 * rs1) + cb1;
            }
            if (RESID) {
                float2 q0 = *(const float2*)&resid[base0];
                float2 q1 = *(const float2*)&resid[base1];
                r0.x += q0.x; r0.y += q0.y;
                r1.x += q1.x; r1.y += q1.y;
            }
            *(float2*)&out[base0] = r0;
            *(float2*)&out[base1] = r1;
        }
    }
}

// ---------------------------------------------------------------------------
// 2) Depthwise 3x3 conv, SAME padding
// ---------------------------------------------------------------------------
__global__ __launch_bounds__(256) void dwconv_k(const float* __restrict__ in,
                                                const float* __restrict__ wd,
                                                float* __restrict__ out,
                                                int CHN)
{
    __shared__ float t[10][34];
    int plane = blockIdx.z;
    int ch    = plane % CHN;
    size_t base = (size_t)plane * HW;

    int x0 = blockIdx.x * 32;
    int y0 = blockIdx.y * 8;
    int tid = threadIdx.y * 32 + threadIdx.x;

    for (int idx = tid; idx < 340; idx += 256) {
        int r = idx / 34, c = idx % 34;
        int gy = y0 - 1 + r, gx = x0 - 1 + c;
        float v = 0.f;
        if (gy >= 0 && gy < 128 && gx >= 0 && gx < 128)
            v = in[base + gy * 128 + gx];
        t[r][c] = v;
    }
    __syncthreads();

    float w0 = wd[ch * 9 + 0], w1 = wd[ch * 9 + 1], w2 = wd[ch * 9 + 2];
    float w3 = wd[ch * 9 + 3], w4 = wd[ch * 9 + 4], w5 = wd[ch * 9 + 5];
    float w6 = wd[ch * 9 + 6], w7 = wd[ch * 9 + 7], w8 = wd[ch * 9 + 8];

    int ty = threadIdx.y, tx = threadIdx.x;
    float acc = t[ty + 0][tx + 0] * w0 + t[ty + 0][tx + 1] * w1 + t[ty + 0][tx + 2] * w2
              + t[ty + 1][tx + 0] * w3 + t[ty + 1][tx + 1] * w4 + t[ty + 1][tx + 2] * w5
              + t[ty + 2][tx + 0] * w6 + t[ty + 2][tx + 1] * w7 + t[ty + 2][tx + 2] * w8;
    out[base + (y0 + ty) * 128 + (x0 + tx)] = acc;
}

// ---------------------------------------------------------------------------
// 3) Attention logits (float4 vectorized) + fused sq-norm partials
// ---------------------------------------------------------------------------
__global__ __launch_bounds__(256) void attn_logits_k(const float* __restrict__ qkv)
{
    int seg = blockIdx.x;
    int bh  = blockIdx.y;
    int b = bh >> 3, h = bh & 7;
    const float* qb = qkv + ((size_t)b * 384 + h * DHEAD) * HW + seg * 128;
    const float* kb = qkv + ((size_t)b * 384 + 128 + h * DHEAD) * HW + seg * 128;

    __shared__ __align__(16) float qs[16][132];
    __shared__ __align__(16) float ks[16][132];

    int tid = threadIdx.x;
#pragma unroll
    for (int t = 0; t < 8; t++) {
        int idx = tid + t * 256;
        int row = idx >> 7, n = idx & 127;
        qs[row][n] = qb[(size_t)row * HW + n];
        ks[row][n] = kb[(size_t)row * HW + n];
    }
    __syncthreads();

    int i = tid >> 4, j = tid & 15;
    bool diag = (i == j);
    const float4* q4 = (const float4*)&qs[i][0];
    const float4* k4 = (const float4*)&ks[j][0];
    float acc = 0.f, q2 = 0.f, k2 = 0.f;
#pragma unroll 8
    for (int n4 = 0; n4 < 32; n4++) {
        float4 a = q4[n4];
        float4 c = k4[n4];
        acc = fmaf(a.x, c.x, acc); acc = fmaf(a.y, c.y, acc);
        acc = fmaf(a.z, c.z, acc); acc = fmaf(a.w, c.w, acc);
        if (diag) {
            q2 = fmaf(a.x, a.x, q2); q2 = fmaf(a.y, a.y, q2);
            q2 = fmaf(a.z, a.z, q2); q2 = fmaf(a.w, a.w, q2);
            k2 = fmaf(c.x, c.x, k2); k2 = fmaf(c.y, c.y, k2);
            k2 = fmaf(c.z, c.z, k2); k2 = fmaf(c.w, c.w, k2);
        }
    }

    int slot = bh * ALOG_SEGS + seg;
    g_partS[(size_t)slot * 256 + tid] = acc;
    if (diag) {
        g_partQ2[slot * 16 + i] = q2;
        g_partK2[slot * 16 + i] = k2;
    }
}

// ---------------------------------------------------------------------------
// 4) Finalize: reduce segments, l2norm scale, temperature, softmax
// ---------------------------------------------------------------------------
__global__ __launch_bounds__(256) void attn_finalize_k(const float* __restrict__ temp)
{
    int bh = blockIdx.x;
    int h = bh & 7;
    int i = threadIdx.x >> 4, j = threadIdx.x & 15;

    float s = 0.f, q2 = 0.f, k2 = 0.f;
    for (int seg = 0; seg < ALOG_SEGS; seg++) {
        int slot = bh * ALOG_SEGS + seg;
        s  += g_partS [(size_t)slot * 256 + threadIdx.x];
        q2 += g_partQ2[slot * 16 + i];
        k2 += g_partK2[slot * 16 + j];
    }
    float rq = 1.f / fmaxf(sqrtf(q2), 1e-12f);
    float rk = 1.f / fmaxf(sqrtf(k2), 1e-12f);
    s = s * rq * rk * temp[h];

    float m = s;
    m = fmaxf(m, __shfl_xor_sync(0xffffffffu, m, 8, 16));
    m = fmaxf(m, __shfl_xor_sync(0xffffffffu, m, 4, 16));
    m = fmaxf(m, __shfl_xor_sync(0xffffffffu, m, 2, 16));
    m = fmaxf(m, __shfl_xor_sync(0xffffffffu, m, 1, 16));
    float e = expf(s - m);
    float sum = e;
    sum += __shfl_xor_sync(0xffffffffu, sum, 8, 16);
    sum += __shfl_xor_sync(0xffffffffu, sum, 4, 16);
    sum += __shfl_xor_sync(0xffffffffu, sum, 2, 16);
    sum += __shfl_xor_sync(0xffffffffu, sum, 1, 16);
    g_attn[bh * 256 + threadIdx.x] = e / sum;
}

// ---------------------------------------------------------------------------
// 5) Effective proj weights, written directly in packed tf32 fragment layout
// ---------------------------------------------------------------------------
__global__ __launch_bounds__(256) void weff_k(const float* __restrict__ proj_w)
{
    int b = blockIdx.x, h = blockIdx.y;
    __shared__ float at[16][16];
    __shared__ float pw[128][16];
    int tid = threadIdx.x;

    at[tid >> 4][tid & 15] = g_attn[(b * 8 + h) * 256 + tid];
#pragma unroll
    for (int t = 0; t < 8; t++) {
        int idx = tid + t * 256;
        int o = idx >> 4, i = idx & 15;
        pw[o][i] = proj_w[o * 128 + h * 16 + i];
    }
    __syncthreads();

#pragma unroll
    for (int t = 0; t < 8; t++) {
        int idx = tid + t * 256;
        int o = idx >> 4, e = idx & 15;
        float s = 0.f;
#pragma unroll
        for (int i = 0; i < 16; i++) s = fmaf(pw[o][i], at[i][e], s);
        g_WeffP[b * 16384 + packA(o, h * 16 + e, 128)] = f2tf(s);
    }
}

// ---------------------------------------------------------------------------
// Launch
// ---------------------------------------------------------------------------
extern "C" void kernel_launch(void* const* d_in, const int* in_sizes, int n_in,
                              void* d_out, int out_size)
{
    const float* x      = (const float*)d_in[0];
    const float* ln1_w  = (const float*)d_in[1];
    const float* ln1_b  = (const float*)d_in[2];
    const float* temp   = (const float*)d_in[3];
    const float* qkv_pw = (const float*)d_in[4];
    const float* qkv_dw = (const float*)d_in[5];
    const float* proj_w = (const float*)d_in[6];
    const float* ln2_w  = (const float*)d_in[7];
    const float* ln2_b  = (const float*)d_in[8];
    const float* g1_w   = (const float*)d_in[9];
    const float* gd_w   = (const float*)d_in[10];
    const float* g2_w   = (const float*)d_in[11];
    float* out = (float*)d_out;

    float *bufA, *bufB, *rs, *cb;
    uint32_t *WqP, *Wg1P, *Wg2P, *WeffP;
    cudaGetSymbolAddress((void**)&bufA,  g_bufA);
    cudaGetSymbolAddress((void**)&bufB,  g_bufB);
    cudaGetSymbolAddress((void**)&WqP,   g_WqP);
    cudaGetSymbolAddress((void**)&Wg1P,  g_Wg1P);
    cudaGetSymbolAddress((void**)&Wg2P,  g_Wg2P);
    cudaGetSymbolAddress((void**)&WeffP, g_WeffP);
    cudaGetSymbolAddress((void**)&rs,    g_rs);
    cudaGetSymbolAddress((void**)&cb,    g_cb);

    dim3 b256(256);

    prep_w_k<<<128, b256>>>(qkv_pw, ln1_w, ln1_b, g1_w, ln2_w, ln2_b, g2_w);

    // --- MDTA ---
    gemm_tc<1, false><<<dim3(HW / BN, 384 / BM, BATCH), b256>>>(
        WqP, x, rs, cb, nullptr, bufA, 384, 128, 128, 0);
    dwconv_k<<<dim3(4, 16, BATCH * 384), dim3(32, 8)>>>(bufA, qkv_dw, bufB, 384);
    attn_logits_k<<<dim3(ALOG_SEGS, 32), b256>>>(bufB);
    attn_finalize_k<<<32, b256>>>(temp);
    weff_k<<<dim3(4, 8), b256>>>(proj_w);
    gemm_tc<0, true><<<dim3(HW / BN, 1, BATCH), b256>>>(
        WeffP, bufB + (size_t)256 * HW, nullptr, nullptr, x, out, 128, 128, 384, 16384);

    // --- GDFN ---
    gemm_tc<1, false><<<dim3(HW / BN, 512 / BM, BATCH), b256>>>(
        Wg1P, out, rs + 384, cb + 384, nullptr, bufA, 512, 128, 128, 0);
    dwconv_k<<<dim3(4, 16, BATCH * 512), dim3(32, 8)>>>(bufA, gd_w, bufB, 512);
    gemm_tc<2, true><<<dim3(HW / BN, 1, BATCH), b256>>>(
        Wg2P, bufB, nullptr, nullptr, out, out, 128, 256, 512, 0);
}

// round 6
// speedup vs baseline: 1.2727x; 1.2727x over previous
#include <cuda_runtime.h>
#include <cuda_bf16.h>
#include <math.h>
#include <stdint.h>

// ---------------------------------------------------------------------------
// Problem constants (B=4, C=128, H=W=128, NH=8, d=16, GDFN hidden=512)
// ---------------------------------------------------------------------------
#define BATCH 4
#define CH    128
#define HW    16384
#define NHEAD 8
#define DHEAD 16
#define ALOG_SEGS 128

// ---------------------------------------------------------------------------
// Scratch (device globals)
// ---------------------------------------------------------------------------
__device__ float g_bufA[BATCH * 512 * HW];
__device__ float g_bufB[BATCH * 512 * HW];
__device__ float g_partS [32 * ALOG_SEGS * 256];
__device__ float g_partQ2[32 * ALOG_SEGS * 16];
__device__ float g_partK2[32 * ALOG_SEGS * 16];
__device__ float g_attn  [32 * 256];
__device__ float g_WqP [384 * 128];          // qkv weights pre-scaled by ln1_w
__device__ float g_Wg1P[512 * 128];          // g1 weights pre-scaled by ln2_w
__device__ float g_rs  [896];
__device__ float g_cb  [896];
__device__ float g_Weff[BATCH * 128 * 128];  // per-batch proj*attn weights

// ---------------------------------------------------------------------------
// helpers
// ---------------------------------------------------------------------------
__device__ __forceinline__ uint32_t f2tf(float v)
{
    uint32_t r;
    asm("cvt.rna.tf32.f32 %0, %1;" : "=r"(r) : "f"(v));
    return r;
}

__device__ __forceinline__ void mma_tf32(float* d, const uint32_t* a, const uint32_t* b)
{
    asm volatile(
        "mma.sync.aligned.m16n8k8.row.col.f32.tf32.tf32.f32 "
        "{%0,%1,%2,%3},{%4,%5,%6,%7},{%8,%9},{%0,%1,%2,%3};"
        : "+f"(d[0]), "+f"(d[1]), "+f"(d[2]), "+f"(d[3])
        : "r"(a[0]), "r"(a[1]), "r"(a[2]), "r"(a[3]), "r"(b[0]), "r"(b[1]));
}

__device__ __forceinline__ float gelu_exact(float v)
{
    return 0.5f * v * (1.f + erff(v * 0.70710678118654752440f));
}

// ---------------------------------------------------------------------------
// 0) Weight prep: W'[o,c] = W[o,c]*lnw[c]; rowsum; const-bias.
// ---------------------------------------------------------------------------
__global__ __launch_bounds__(256) void prep_w_k(const float* __restrict__ qkv_pw,
                                                const float* __restrict__ ln1w,
                                                const float* __restrict__ ln1b,
                                                const float* __restrict__ g1w,
                                                const float* __restrict__ ln2w,
                                                const float* __restrict__ ln2b)
{
    int row  = blockIdx.x * 8 + (threadIdx.x >> 5);
    int lane = threadIdx.x & 31;
    const float *W, *lw, *lb;
    float* Wp;
    if (row < 384) { W = qkv_pw + (size_t)row * 128; lw = ln1w; lb = ln1b; Wp = g_WqP + (size_t)row * 128; }
    else           { W = g1w + (size_t)(row - 384) * 128; lw = ln2w; lb = ln2b; Wp = g_Wg1P + (size_t)(row - 384) * 128; }

    float rs = 0.f, cb = 0.f;
#pragma unroll
    for (int t = 0; t < 4; t++) {
        int c = lane + t * 32;
        float w = W[c];
        float wp = w * lw[c];
        Wp[c] = wp;
        rs += wp;
        cb += w * lb[c];
    }
#pragma unroll
    for (int o = 16; o > 0; o >>= 1) {
        rs += __shfl_xor_sync(0xffffffffu, rs, o);
        cb += __shfl_xor_sync(0xffffffffu, cb, o);
    }
    if (lane == 0) { g_rs[row] = rs; g_cb[row] = cb; }
}

// ---------------------------------------------------------------------------
// 1) tf32 GEMM: 128x128x16 tiles, 256 threads, 3-buffer smem, 1 sync/stage,
//    2-stage deep LDG prefetch.  MODE 0: plain   MODE 1: LN-in-epilogue
// ---------------------------------------------------------------------------
#define BM  128
#define BN  128
#define BK  16
#define BKP 20
#define BNP 136

template <int MODE, bool RESID>
__global__ __launch_bounds__(256) void gemm_tc(
    const float* __restrict__ W,      // (OC, K) row-major (per-batch via wbstride)
    const float* __restrict__ X,      // (B, XCH, HW)
    const float* __restrict__ rsum,
    const float* __restrict__ cbias,
    const float* __restrict__ resid,
    float* __restrict__ out,          // (B, OC, HW)
    int OC, int K, int XCH, int wbstride)
{
    __shared__ uint32_t Ws[3][BM * BKP];
    __shared__ uint32_t Xs[3][BK * BNP];

    const int b    = blockIdx.z;
    const int n0   = blockIdx.x * BN;
    const int oc0  = blockIdx.y * BM;
    const int tid  = threadIdx.x;
    const int warp = tid >> 5;
    const int lane = tid & 31;
    const int wm   = warp >> 2;
    const int wn   = warp & 3;
    const int gid  = lane >> 2;
    const int tig  = lane & 3;

    const float* Wb = W + (size_t)b * wbstride;
    const float* Xb = X + (size_t)b * XCH * HW;

    float acc[4][4][4];
#pragma unroll
    for (int mt = 0; mt < 4; mt++)
#pragma unroll
        for (int nt = 0; nt < 4; nt++)
#pragma unroll
            for (int r = 0; r < 4; r++) acc[mt][nt][r] = 0.f;

    float cs[4]  = {0.f, 0.f, 0.f, 0.f};
    float cs2[4] = {0.f, 0.f, 0.f, 0.f};

    float4 wreg0[2], xreg0[2], wreg1[2], xreg1[2];

    // loader geometry (per thread, 2 float4 each for W and X)
    const int wr0 = tid >> 2,          wc0 = (tid & 3) << 2;
    const int wr1 = (tid + 256) >> 2,  wc1 = wc0;
    const int xk0 = tid >> 5,          xn0 = (tid & 31) << 2;
    const int xk1 = xk0 + 8,           xn1 = xn0;

#define LDG_SET(WR, XR)                                                        \
    do {                                                                       \
        int k0 = _s * BK;                                                      \
        WR[0] = *(const float4*)&Wb[(size_t)(oc0 + wr0) * K + k0 + wc0];       \
        WR[1] = *(const float4*)&Wb[(size_t)(oc0 + wr1) * K + k0 + wc1];       \
        XR[0] = *(const float4*)&Xb[(size_t)(k0 + xk0) * HW + n0 + xn0];       \
        XR[1] = *(const float4*)&Xb[(size_t)(k0 + xk1) * HW + n0 + xn1];       \
        if (MODE == 1) {                                                       \
            cs[0] += XR[0].x + XR[1].x;                                        \
            cs[1] += XR[0].y + XR[1].y;                                        \
            cs[2] += XR[0].z + XR[1].z;                                        \
            cs[3] += XR[0].w + XR[1].w;                                        \
            cs2[0] = fmaf(XR[0].x, XR[0].x, fmaf(XR[1].x, XR[1].x, cs2[0]));   \
            cs2[1] = fmaf(XR[0].y, XR[0].y, fmaf(XR[1].y, XR[1].y, cs2[1]));   \
            cs2[2] = fmaf(XR[0].z, XR[0].z, fmaf(XR[1].z, XR[1].z, cs2[2]));   \
            cs2[3] = fmaf(XR[0].w, XR[0].w, fmaf(XR[1].w, XR[1].w, cs2[3]));   \
        }                                                                      \
    } while (0)

#define STS_SET(WR, XR)                                                        \
    do {                                                                       \
        int buf = _s % 3;                                                      \
        uint32_t* pw0 = &Ws[buf][wr0 * BKP + wc0];                             \
        pw0[0] = f2tf(WR[0].x); pw0[1] = f2tf(WR[0].y);                        \
        pw0[2] = f2tf(WR[0].z); pw0[3] = f2tf(WR[0].w);                        \
        uint32_t* pw1 = &Ws[buf][wr1 * BKP + wc1];                             \
        pw1[0] = f2tf(WR[1].x); pw1[1] = f2tf(WR[1].y);                        \
        pw1[2] = f2tf(WR[1].z); pw1[3] = f2tf(WR[1].w);                        \
        uint32_t* px0 = &Xs[buf][xk0 * BNP + xn0];                             \
        px0[0] = f2tf(XR[0].x); px0[1] = f2tf(XR[0].y);                        \
        px0[2] = f2tf(XR[0].z); px0[3] = f2tf(XR[0].w);                        \
        uint32_t* px1 = &Xs[buf][xk1 * BNP + xn1];                             \
        px1[0] = f2tf(XR[1].x); px1[1] = f2tf(XR[1].y);                        \
        px1[2] = f2tf(XR[1].z); px1[3] = f2tf(XR[1].w);                        \
    } while (0)

    auto compute = [&](int s) {
        int buf = s % 3;
#pragma unroll
        for (int ks = 0; ks < 2; ks++) {
            uint32_t afr[4][4], bfr[4][2];
#pragma unroll
            for (int mt = 0; mt < 4; mt++) {
                int r = wm * 64 + mt * 16 + gid;
                int c = ks * 8 + tig;
                afr[mt][0] = Ws[buf][r * BKP + c];
                afr[mt][1] = Ws[buf][(r + 8) * BKP + c];
                afr[mt][2] = Ws[buf][r * BKP + c + 4];
                afr[mt][3] = Ws[buf][(r + 8) * BKP + c + 4];
            }
#pragma unroll
            for (int nt = 0; nt < 4; nt++) {
                int col = wn * 32 + nt * 8 + gid;
                bfr[nt][0] = Xs[buf][(ks * 8 + tig) * BNP + col];
                bfr[nt][1] = Xs[buf][(ks * 8 + tig + 4) * BNP + col];
            }
#pragma unroll
            for (int mt = 0; mt < 4; mt++)
#pragma unroll
                for (int nt = 0; nt < 4; nt++)
                    mma_tf32(acc[mt][nt], afr[mt], bfr[nt]);
        }
    };

    const int NS = K >> 4;   // 8 or 16 (even)

    // prologue: ldg(0)->set0, ldg(1)->set1, sts(0, set0)
    { int _s = 0; LDG_SET(wreg0, xreg0); }
    { int _s = 1; LDG_SET(wreg1, xreg1); }
    { int _s = 0; STS_SET(wreg0, xreg0); }
    __syncthreads();

    for (int s = 0; s < NS; s += 2) {
        // even stage s: ldg(s+2)->set0, sts(s+1, set1)
        if (s + 2 < NS) { int _s = s + 2; LDG_SET(wreg0, xreg0); }
        { int _s = s + 1; STS_SET(wreg1, xreg1); }
        __syncthreads();
        compute(s);
        // odd stage s+1: ldg(s+3)->set1, sts(s+2, set0)
        if (s + 3 < NS) { int _s = s + 3; LDG_SET(wreg1, xreg1); }
        if (s + 2 < NS) { int _s = s + 2; STS_SET(wreg0, xreg0); }
        __syncthreads();
        compute(s + 1);
    }
#undef LDG_SET
#undef STS_SET

    // --- MODE 1: per-column LN stats reduction (overlay dead smem) ---
    float* redS  = (float*)&Ws[0][0];        // [8][128]  (8KB <= 10.2KB)
    float* redS2 = (float*)&Ws[1][0];        // [8][128]
    float* muS   = (float*)&Xs[0][0];        // [128]
    float* rsS   = muS + 128;                // [128]
    if (MODE == 1) {
        __syncthreads();
        int jrow = tid >> 5;
        int nc   = (tid & 31) << 2;
#pragma unroll
        for (int c = 0; c < 4; c++) {
            redS [jrow * 128 + nc + c] = cs[c];
            redS2[jrow * 128 + nc + c] = cs2[c];
        }
        __syncthreads();
        if (tid < 128) {
            float s = 0.f, s2 = 0.f;
#pragma unroll
            for (int j = 0; j < 8; j++) {
                s  += redS [j * 128 + tid];
                s2 += redS2[j * 128 + tid];
            }
            float m   = s * (1.f / 128.f);
            float var = s2 * (1.f / 128.f) - m * m;
            muS[tid] = m;
            rsS[tid] = rsqrtf(var + 1e-5f);
        }
        __syncthreads();
    }

    // --- epilogue ---
#pragma unroll
    for (int mt = 0; mt < 4; mt++) {
        int ocl0 = wm * 64 + mt * 16 + gid;
        float rs0 = 0.f, rs1 = 0.f, cb0 = 0.f, cb1 = 0.f;
        if (MODE == 1) {
            rs0 = rsum[oc0 + ocl0];  rs1 = rsum[oc0 + ocl0 + 8];
            cb0 = cbias[oc0 + ocl0]; cb1 = cbias[oc0 + ocl0 + 8];
        }
#pragma unroll
        for (int nt = 0; nt < 4; nt++) {
            int nl = wn * 32 + nt * 8 + tig * 2;
            size_t base0 = ((size_t)b * OC + oc0 + ocl0) * HW + n0 + nl;
            size_t base1 = ((size_t)b * OC + oc0 + ocl0 + 8) * HW + n0 + nl;
            float2 r0 = make_float2(acc[mt][nt][0], acc[mt][nt][1]);
            float2 r1 = make_float2(acc[mt][nt][2], acc[mt][nt][3]);
            if (MODE == 1) {
                float mu0 = muS[nl], mu1 = muS[nl + 1];
                float rd0 = rsS[nl], rd1 = rsS[nl + 1];
                r0.x = rd0 * (r0.x - mu0 * rs0) + cb0;
                r0.y = rd1 * (r0.y - mu1 * rs0) + cb0;
                r1.x = rd0 * (r1.x - mu0 * rs1) + cb1;
                r1.y = rd1 * (r1.y - mu1 * rs1) + cb1;
            }
            if (RESID) {
                float2 q0 = *(const float2*)&resid[base0];
                float2 q1 = *(const float2*)&resid[base1];
                r0.x += q0.x; r0.y += q0.y;
                r1.x += q1.x; r1.y += q1.y;
            }
            *(float2*)&out[base0] = r0;
            *(float2*)&out[base1] = r1;
        }
    }
}

// ---------------------------------------------------------------------------
// 2) Depthwise 3x3 conv, full-width 128x16 tiles, float4 I/O.
//    grid (8 ytiles, B*CHN planes), 256 threads.
// ---------------------------------------------------------------------------
__global__ __launch_bounds__(256) void dwconv_k(const float* __restrict__ in,
                                                const float* __restrict__ wd,
                                                float* __restrict__ out,
                                                int CHN)
{
    __shared__ float t[18][136];     // rows y0-1..y0+16, data at cols [4..131]
    int plane = blockIdx.y;
    int ch    = plane % CHN;
    size_t base = (size_t)plane * HW;
    int y0  = blockIdx.x * 16;
    int tid = threadIdx.x;

    if (tid < 36) t[tid >> 1][3 + (tid & 1) * 129] = 0.f;
#pragma unroll
    for (int i = tid; i < 576; i += 256) {
        int r = i >> 5, c4 = (i & 31) << 2;
        int gy = y0 - 1 + r;
        float4 v = make_float4(0.f, 0.f, 0.f, 0.f);
        if (gy >= 0 && gy < 128) v = *(const float4*)&in[base + gy * 128 + c4];
        *(float4*)&t[r][4 + c4] = v;
    }
    __syncthreads();

    float w[9];
#pragma unroll
    for (int j = 0; j < 9; j++) w[j] = wd[ch * 9 + j];

    int x4 = (tid & 31) << 2;
    int r0 = tid >> 5;
#pragma unroll
    for (int rr = 0; rr < 16; rr += 8) {
        int row = r0 + rr;
        float4 o = make_float4(0.f, 0.f, 0.f, 0.f);
#pragma unroll
        for (int dy = 0; dy < 3; dy++) {
            const float* tr = &t[row + dy][4 + x4];
            float m0 = tr[-1], m1 = tr[0], m2 = tr[1], m3 = tr[2], m4 = tr[3], m5 = tr[4];
            float a = w[dy * 3 + 0], bw = w[dy * 3 + 1], c = w[dy * 3 + 2];
            o.x = fmaf(a, m0, fmaf(bw, m1, fmaf(c, m2, o.x)));
            o.y = fmaf(a, m1, fmaf(bw, m2, fmaf(c, m3, o.y)));
            o.z = fmaf(a, m2, fmaf(bw, m3, fmaf(c, m4, o.z)));
            o.w = fmaf(a, m3, fmaf(bw, m4, fmaf(c, m5, o.w)));
        }
        *(float4*)&out[base + (y0 + row) * 128 + x4] = o;
    }
}

// ---------------------------------------------------------------------------
// 2b) GDFN: dwconv of x1 and x2 channels + gelu gate, fused.
//     in: 512ch, out: 256ch = gelu(dw(x1)) * dw(x2). grid (8, B*256).
// ---------------------------------------------------------------------------
__global__ __launch_bounds__(256) void dwgate_k(const float* __restrict__ in,
                                                const float* __restrict__ wd,
                                                float* __restrict__ out)
{
    __shared__ float t1[18][136];
    __shared__ float t2[18][136];
    int plane = blockIdx.y;              // b*256 + ch
    int b  = plane >> 8, ch = plane & 255;
    size_t base1 = ((size_t)b * 512 + ch) * HW;
    size_t base2 = ((size_t)b * 512 + 256 + ch) * HW;
    size_t baseo = ((size_t)b * 256 + ch) * HW;
    int y0  = blockIdx.x * 16;
    int tid = threadIdx.x;

    if (tid < 36) {
        t1[tid >> 1][3 + (tid & 1) * 129] = 0.f;
        t2[tid >> 1][3 + (tid & 1) * 129] = 0.f;
    }
#pragma unroll
    for (int i = tid; i < 576; i += 256) {
        int r = i >> 5, c4 = (i & 31) << 2;
        int gy = y0 - 1 + r;
        float4 v1 = make_float4(0.f, 0.f, 0.f, 0.f);
        float4 v2 = make_float4(0.f, 0.f, 0.f, 0.f);
        if (gy >= 0 && gy < 128) {
            v1 = *(const float4*)&in[base1 + gy * 128 + c4];
            v2 = *(const float4*)&in[base2 + gy * 128 + c4];
        }
        *(float4*)&t1[r][4 + c4] = v1;
        *(float4*)&t2[r][4 + c4] = v2;
    }
    __syncthreads();

    float wA[9], wB[9];
#pragma unroll
    for (int j = 0; j < 9; j++) { wA[j] = wd[ch * 9 + j]; wB[j] = wd[(256 + ch) * 9 + j]; }

    int x4 = (tid & 31) << 2;
    int r0 = tid >> 5;
#pragma unroll
    for (int rr = 0; rr < 16; rr += 8) {
        int row = r0 + rr;
        float4 o1 = make_float4(0.f, 0.f, 0.f, 0.f);
        float4 o2 = make_float4(0.f, 0.f, 0.f, 0.f);
#pragma unroll
        for (int dy = 0; dy < 3; dy++) {
            {
                const float* tr = &t1[row + dy][4 + x4];
                float m0 = tr[-1], m1 = tr[0], m2 = tr[1], m3 = tr[2], m4 = tr[3], m5 = tr[4];
                float a = wA[dy * 3 + 0], bw = wA[dy * 3 + 1], c = wA[dy * 3 + 2];
                o1.x = fmaf(a, m0, fmaf(bw, m1, fmaf(c, m2, o1.x)));
                o1.y = fmaf(a, m1, fmaf(bw, m2, fmaf(c, m3, o1.y)));
                o1.z = fmaf(a, m2, fmaf(bw, m3, fmaf(c, m4, o1.z)));
                o1.w = fmaf(a, m3, fmaf(bw, m4, fmaf(c, m5, o1.w)));
            }
            {
                const float* tr = &t2[row + dy][4 + x4];
                float m0 = tr[-1], m1 = tr[0], m2 = tr[1], m3 = tr[2], m4 = tr[3], m5 = tr[4];
                float a = wB[dy * 3 + 0], bw = wB[dy * 3 + 1], c = wB[dy * 3 + 2];
                o2.x = fmaf(a, m0, fmaf(bw, m1, fmaf(c, m2, o2.x)));
                o2.y = fmaf(a, m1, fmaf(bw, m2, fmaf(c, m3, o2.y)));
                o2.z = fmaf(a, m2, fmaf(bw, m3, fmaf(c, m4, o2.z)));
                o2.w = fmaf(a, m3, fmaf(bw, m4, fmaf(c, m5, o2.w)));
            }
        }
        float4 g;
        g.x = gelu_exact(o1.x) * o2.x;
        g.y = gelu_exact(o1.y) * o2.y;
        g.z = gelu_exact(o1.z) * o2.z;
        g.w = gelu_exact(o1.w) * o2.w;
        *(float4*)&out[baseo + (y0 + row) * 128 + x4] = g;
    }
}

// ---------------------------------------------------------------------------
// 3) Attention logits (float4 vectorized) + fused sq-norm partials
// ---------------------------------------------------------------------------
__global__ __launch_bounds__(256) void attn_logits_k(const float* __restrict__ qkv)
{
    int seg = blockIdx.x;
    int bh  = blockIdx.y;
    int b = bh >> 3, h = bh & 7;
    const float* qb = qkv + ((size_t)b * 384 + h * DHEAD) * HW + seg * 128;
    const float* kb = qkv + ((size_t)b * 384 + 128 + h * DHEAD) * HW + seg * 128;

    __shared__ __align__(16) float qs[16][132];
    __shared__ __align__(16) float ks[16][132];

    int tid = threadIdx.x;
#pragma unroll
    for (int t = 0; t < 8; t++) {
        int idx = tid + t * 256;
        int row = idx >> 7, n = idx & 127;
        qs[row][n] = qb[(size_t)row * HW + n];
        ks[row][n] = kb[(size_t)row * HW + n];
    }
    __syncthreads();

    int i = tid >> 4, j = tid & 15;
    bool diag = (i == j);
    const float4* q4 = (const float4*)&qs[i][0];
    const float4* k4 = (const float4*)&ks[j][0];
    float acc = 0.f, q2 = 0.f, k2 = 0.f;
#pragma unroll 8
    for (int n4 = 0; n4 < 32; n4++) {
        float4 a = q4[n4];
        float4 c = k4[n4];
        acc = fmaf(a.x, c.x, acc); acc = fmaf(a.y, c.y, acc);
        acc = fmaf(a.z, c.z, acc); acc = fmaf(a.w, c.w, acc);
        if (diag) {
            q2 = fmaf(a.x, a.x, q2); q2 = fmaf(a.y, a.y, q2);
            q2 = fmaf(a.z, a.z, q2); q2 = fmaf(a.w, a.w, q2);
            k2 = fmaf(c.x, c.x, k2); k2 = fmaf(c.y, c.y, k2);
            k2 = fmaf(c.z, c.z, k2); k2 = fmaf(c.w, c.w, k2);
        }
    }

    int slot = bh * ALOG_SEGS + seg;
    g_partS[(size_t)slot * 256 + tid] = acc;
    if (diag) {
        g_partQ2[slot * 16 + i] = q2;
        g_partK2[slot * 16 + i] = k2;
    }
}

// ---------------------------------------------------------------------------
// 4) Finalize: reduce segments, l2norm scale, temperature, softmax
// ---------------------------------------------------------------------------
__global__ __launch_bounds__(256) void attn_finalize_k(const float* __restrict__ temp)
{
    int bh = blockIdx.x;
    int h = bh & 7;
    int i = threadIdx.x >> 4, j = threadIdx.x & 15;

    float s = 0.f, q2 = 0.f, k2 = 0.f;
    for (int seg = 0; seg < ALOG_SEGS; seg++) {
        int slot = bh * ALOG_SEGS + seg;
        s  += g_partS [(size_t)slot * 256 + threadIdx.x];
        q2 += g_partQ2[slot * 16 + i];
        k2 += g_partK2[slot * 16 + j];
    }
    float rq = 1.f / fmaxf(sqrtf(q2), 1e-12f);
    float rk = 1.f / fmaxf(sqrtf(k2), 1e-12f);
    s = s * rq * rk * temp[h];

    float m = s;
    m = fmaxf(m, __shfl_xor_sync(0xffffffffu, m, 8, 16));
    m = fmaxf(m, __shfl_xor_sync(0xffffffffu, m, 4, 16));
    m = fmaxf(m, __shfl_xor_sync(0xffffffffu, m, 2, 16));
    m = fmaxf(m, __shfl_xor_sync(0xffffffffu, m, 1, 16));
    float e = expf(s - m);
    float sum = e;
    sum += __shfl_xor_sync(0xffffffffu, sum, 8, 16);
    sum += __shfl_xor_sync(0xffffffffu, sum, 4, 16);
    sum += __shfl_xor_sync(0xffffffffu, sum, 2, 16);
    sum += __shfl_xor_sync(0xffffffffu, sum, 1, 16);
    g_attn[bh * 256 + threadIdx.x] = e / sum;
}

// ---------------------------------------------------------------------------
// 5) Effective proj weights (plain row-major, per batch)
// ---------------------------------------------------------------------------
__global__ __launch_bounds__(256) void weff_k(const float* __restrict__ proj_w)
{
    int b = blockIdx.x, h = blockIdx.y;
    __shared__ float at[16][16];
    __shared__ float pw[128][16];
    int tid = threadIdx.x;

    at[tid >> 4][tid & 15] = g_attn[(b * 8 + h) * 256 + tid];
#pragma unroll
    for (int t = 0; t < 8; t++) {
        int idx = tid + t * 256;
        int o = idx >> 4, i = idx & 15;
        pw[o][i] = proj_w[o * 128 + h * 16 + i];
    }
    __syncthreads();

#pragma unroll
    for (int t = 0; t < 8; t++) {
        int idx = tid + t * 256;
        int o = idx >> 4, e = idx & 15;
        float s = 0.f;
#pragma unroll
        for (int i = 0; i < 16; i++) s = fmaf(pw[o][i], at[i][e], s);
        g_Weff[((size_t)b * 128 + o) * 128 + h * 16 + e] = s;
    }
}

// ---------------------------------------------------------------------------
// Launch
// ---------------------------------------------------------------------------
extern "C" void kernel_launch(void* const* d_in, const int* in_sizes, int n_in,
                              void* d_out, int out_size)
{
    const float* x      = (const float*)d_in[0];
    const float* ln1_w  = (const float*)d_in[1];
    const float* ln1_b  = (const float*)d_in[2];
    const float* temp   = (const float*)d_in[3];
    const float* qkv_pw = (const float*)d_in[4];
    const float* qkv_dw = (const float*)d_in[5];
    const float* proj_w = (const float*)d_in[6];
    const float* ln2_w  = (const float*)d_in[7];
    const float* ln2_b  = (const float*)d_in[8];
    const float* g1_w   = (const float*)d_in[9];
    const float* gd_w   = (const float*)d_in[10];
    const float* g2_w   = (const float*)d_in[11];
    float* out = (float*)d_out;

    float *bufA, *bufB, *WqP, *Wg1P, *rs, *cb, *Weff;
    cudaGetSymbolAddress((void**)&bufA, g_bufA);
    cudaGetSymbolAddress((void**)&bufB, g_bufB);
    cudaGetSymbolAddress((void**)&WqP,  g_WqP);
    cudaGetSymbolAddress((void**)&Wg1P, g_Wg1P);
    cudaGetSymbolAddress((void**)&rs,   g_rs);
    cudaGetSymbolAddress((void**)&cb,   g_cb);
    cudaGetSymbolAddress((void**)&Weff, g_Weff);

    dim3 b256(256);

    prep_w_k<<<112, b256>>>(qkv_pw, ln1_w, ln1_b, g1_w, ln2_w, ln2_b);

    // --- MDTA ---
    gemm_tc<1, false><<<dim3(HW / BN, 384 / BM, BATCH), b256>>>(
        WqP, x, rs, cb, nullptr, bufA, 384, 128, 128, 0);
    dwconv_k<<<dim3(8, BATCH * 384), b256>>>(bufA, qkv_dw, bufB, 384);
    attn_logits_k<<<dim3(ALOG_SEGS, 32), b256>>>(bufB);
    attn_finalize_k<<<32, b256>>>(temp);
    weff_k<<<dim3(4, 8), b256>>>(proj_w);
    // x2 = x + Weff_b * v   (v = channels 256..383 of bufB)
    gemm_tc<0, true><<<dim3(HW / BN, 1, BATCH), b256>>>(
        Weff, bufB + (size_t)256 * HW, nullptr, nullptr, x, out, 128, 128, 384, 128 * 128);

    // --- GDFN ---
    gemm_tc<1, false><<<dim3(HW / BN, 512 / BM, BATCH), b256>>>(
        Wg1P, out, rs + 384, cb + 384, nullptr, bufA, 512, 128, 128, 0);
    dwgate_k<<<dim3(8, BATCH * 256), b256>>>(bufA, gd_w, bufB);
    gemm_tc<0, true><<<dim3(HW / BN, 1, BATCH), b256>>>(
        g2_w, bufB, nullptr, nullptr, out, out, 128, 256, 256, 0);
}

// round 7
// speedup vs baseline: 1.6457x; 1.2930x over previous
#include <cuda_runtime.h>
#include <cuda_bf16.h>
#include <math.h>
#include <stdint.h>

// ---------------------------------------------------------------------------
// Problem constants (B=4, C=128, H=W=128, NH=8, d=16, GDFN hidden=512)
// ---------------------------------------------------------------------------
#define BATCH 4
#define CH    128
#define HW    16384
#define NHEAD 8
#define DHEAD 16
#define ALOG_SEGS 128

// ---------------------------------------------------------------------------
// Scratch (device globals)
// ---------------------------------------------------------------------------
__device__ float g_bufA[BATCH * 512 * HW];
__device__ float g_bufB[BATCH * 512 * HW];
__device__ float g_mu  [BATCH * HW];
__device__ float g_rstd[BATCH * HW];
__device__ float g_partS [32 * ALOG_SEGS * 256];
__device__ float g_partQ2[32 * ALOG_SEGS * 16];
__device__ float g_partK2[32 * ALOG_SEGS * 16];
__device__ float g_attn  [32 * 256];
__device__ float g_WqP [384 * 128];          // qkv weights, ln1-scaled, tf32-rounded
__device__ float g_Wg1P[512 * 128];          // g1 weights, ln2-scaled, tf32-rounded
__device__ float g_Wg2P[128 * 256];          // g2 weights, tf32-rounded
__device__ float g_rs  [896];
__device__ float g_cb  [896];
__device__ float g_Weff[BATCH * 128 * 128];  // per-batch proj*attn, tf32-rounded

// ---------------------------------------------------------------------------
// helpers
// ---------------------------------------------------------------------------
__device__ __forceinline__ uint32_t f2tf(float v)
{
    uint32_t r;
    asm("cvt.rna.tf32.f32 %0, %1;" : "=r"(r) : "f"(v));
    return r;
}

__device__ __forceinline__ void mma_tf32(float* d, const uint32_t* a, const uint32_t* b)
{
    asm volatile(
        "mma.sync.aligned.m16n8k8.row.col.f32.tf32.tf32.f32 "
        "{%0,%1,%2,%3},{%4,%5,%6,%7},{%8,%9},{%0,%1,%2,%3};"
        : "+f"(d[0]), "+f"(d[1]), "+f"(d[2]), "+f"(d[3])
        : "r"(a[0]), "r"(a[1]), "r"(a[2]), "r"(a[3]), "r"(b[0]), "r"(b[1]));
}

__device__ __forceinline__ void cp16(uint32_t dst_smem, const void* src)
{
    asm volatile("cp.async.ca.shared.global [%0], [%1], 16;" :: "r"(dst_smem), "l"(src));
}
__device__ __forceinline__ void cp_commit()
{
    asm volatile("cp.async.commit_group;");
}
template <int N>
__device__ __forceinline__ void cp_wait()
{
    asm volatile("cp.async.wait_group %0;" :: "n"(N));
}

__device__ __forceinline__ float gelu_exact(float v)
{
    return 0.5f * v * (1.f + erff(v * 0.70710678118654752440f));
}

// ---------------------------------------------------------------------------
// 0a) Weight prep: scale by LN weight, tf32-round, rowsum/const-bias; pack g2.
//     1024 warp-rows: 0..383 qkv | 384..895 g1 | 896..1023 g2
// ---------------------------------------------------------------------------
__global__ __launch_bounds__(256) void prep_w_k(const float* __restrict__ qkv_pw,
                                                const float* __restrict__ ln1w,
                                                const float* __restrict__ ln1b,
                                                const float* __restrict__ g1w,
                                                const float* __restrict__ ln2w,
                                                const float* __restrict__ ln2b,
                                                const float* __restrict__ g2w)
{
    int row  = blockIdx.x * 8 + (threadIdx.x >> 5);
    int lane = threadIdx.x & 31;

    if (row < 896) {
        const float *W, *lw, *lb;
        float* Wp;
        int rl;
        if (row < 384) { W = qkv_pw + (size_t)row * 128; lw = ln1w; lb = ln1b; Wp = g_WqP + (size_t)row * 128; rl = row; }
        else           { W = g1w + (size_t)(row - 384) * 128; lw = ln2w; lb = ln2b; Wp = g_Wg1P + (size_t)(row - 384) * 128; rl = row - 384; }
        (void)rl;
        float rs = 0.f, cb = 0.f;
#pragma unroll
        for (int t = 0; t < 4; t++) {
            int c = lane + t * 32;
            float w = W[c];
            float wp = __uint_as_float(f2tf(w * lw[c]));
            Wp[c] = wp;
            rs += wp;                       // rowsum of the ROUNDED weights
            cb += w * lb[c];
        }
#pragma unroll
        for (int o = 16; o > 0; o >>= 1) {
            rs += __shfl_xor_sync(0xffffffffu, rs, o);
            cb += __shfl_xor_sync(0xffffffffu, cb, o);
        }
        if (lane == 0) { g_rs[row] = rs; g_cb[row] = cb; }
    } else {
        int r = row - 896;
#pragma unroll
        for (int t = 0; t < 8; t++) {
            int c = lane + t * 32;
            g_Wg2P[r * 256 + c] = __uint_as_float(f2tf(g2w[r * 256 + c]));
        }
    }
}

// ---------------------------------------------------------------------------
// 0b) Per-pixel LayerNorm stats, float4 vectorized. grid (16, B), 256 thr.
// ---------------------------------------------------------------------------
__global__ __launch_bounds__(256) void ln_stats_k(const float* __restrict__ x,
                                                  float* __restrict__ mu,
                                                  float* __restrict__ rstd)
{
    int b  = blockIdx.y;
    int n4 = blockIdx.x * 256 + threadIdx.x;
    const float4* xb = (const float4*)(x + (size_t)b * CH * HW) + n4;
    float4 s  = make_float4(0.f, 0.f, 0.f, 0.f);
    float4 s2 = make_float4(0.f, 0.f, 0.f, 0.f);
#pragma unroll 8
    for (int c = 0; c < CH; c++) {
        float4 v = xb[(size_t)c * (HW / 4)];
        s.x += v.x; s.y += v.y; s.z += v.z; s.w += v.w;
        s2.x = fmaf(v.x, v.x, s2.x); s2.y = fmaf(v.y, v.y, s2.y);
        s2.z = fmaf(v.z, v.z, s2.z); s2.w = fmaf(v.w, v.w, s2.w);
    }
    float4 m, r;
    m.x = s.x * (1.f / CH); m.y = s.y * (1.f / CH);
    m.z = s.z * (1.f / CH); m.w = s.w * (1.f / CH);
    r.x = rsqrtf(s2.x * (1.f / CH) - m.x * m.x + 1e-5f);
    r.y = rsqrtf(s2.y * (1.f / CH) - m.y * m.y + 1e-5f);
    r.z = rsqrtf(s2.z * (1.f / CH) - m.z * m.z + 1e-5f);
    r.w = rsqrtf(s2.w * (1.f / CH) - m.w * m.w + 1e-5f);
    *(float4*)&mu  [b * HW + n4 * 4] = m;
    *(float4*)&rstd[b * HW + n4 * 4] = r;
}

// ---------------------------------------------------------------------------
// 1) tf32 GEMM: 128x128x16 tiles, 256 threads, cp.async 3-buffer pipeline.
//    W must be pre-tf32-rounded. X is consumed as raw fp32 (tensor-core tf32
//    truncation).  MODE 0: plain   MODE 1: LN-in-epilogue (mu/rstd global)
// ---------------------------------------------------------------------------
#define BM  128
#define BN  128
#define BK  16
#define BKP 20
#define BNP 136

template <int MODE, bool RESID>
__global__ __launch_bounds__(256) void gemm_tc(
    const float* __restrict__ W,      // (OC, K) row-major (per-batch via wbstride)
    const float* __restrict__ X,      // (B, XCH, HW)
    const float* __restrict__ mu,     // MODE 1
    const float* __restrict__ rstd,   // MODE 1
    const float* __restrict__ rsum,   // MODE 1
    const float* __restrict__ cbias,  // MODE 1
    const float* __restrict__ resid,
    float* __restrict__ out,          // (B, OC, HW)
    int OC, int K, int XCH, int wbstride)
{
    __shared__ uint32_t Ws[3][BM * BKP];
    __shared__ uint32_t Xs[3][BK * BNP];

    const int b    = blockIdx.z;
    const int n0   = blockIdx.x * BN;
    const int oc0  = blockIdx.y * BM;
    const int tid  = threadIdx.x;
    const int warp = tid >> 5;
    const int lane = tid & 31;
    const int wm   = warp >> 2;
    const int wn   = warp & 3;
    const int gid  = lane >> 2;
    const int tig  = lane & 3;

    const float* Wb = W + (size_t)b * wbstride;
    const float* Xb = X + (size_t)b * XCH * HW;

    const uint32_t ws_base = (uint32_t)__cvta_generic_to_shared(&Ws[0][0]);
    const uint32_t xs_base = (uint32_t)__cvta_generic_to_shared(&Xs[0][0]);

    // loader geometry: 4 x 16B per thread per stage
    const int wrow = tid >> 2, wcc = (tid & 3) << 2;    // W rows wrow, wrow+64
    const int xrow = tid >> 5, xcc = (tid & 31) << 2;   // X rows xrow, xrow+8

    float acc[4][4][4];
#pragma unroll
    for (int mt = 0; mt < 4; mt++)
#pragma unroll
        for (int nt = 0; nt < 4; nt++)
#pragma unroll
            for (int r = 0; r < 4; r++) acc[mt][nt][r] = 0.f;

    auto issue = [&](int s) {
        int buf = s % 3;
        int k0  = s * BK;
        cp16(ws_base + (uint32_t)(buf * (BM * BKP) + wrow * BKP + wcc) * 4,
             &Wb[(size_t)(oc0 + wrow) * K + k0 + wcc]);
        cp16(ws_base + (uint32_t)(buf * (BM * BKP) + (wrow + 64) * BKP + wcc) * 4,
             &Wb[(size_t)(oc0 + wrow + 64) * K + k0 + wcc]);
        cp16(xs_base + (uint32_t)(buf * (BK * BNP) + xrow * BNP + xcc) * 4,
             &Xb[(size_t)(k0 + xrow) * HW + n0 + xcc]);
        cp16(xs_base + (uint32_t)(buf * (BK * BNP) + (xrow + 8) * BNP + xcc) * 4,
             &Xb[(size_t)(k0 + xrow + 8) * HW + n0 + xcc]);
        cp_commit();
    };

    auto compute = [&](int s) {
        int buf = s % 3;
#pragma unroll
        for (int ks = 0; ks < 2; ks++) {
            uint32_t afr[4][4], bfr[4][2];
#pragma unroll
            for (int mt = 0; mt < 4; mt++) {
                int r = wm * 64 + mt * 16 + gid;
                int c = ks * 8 + tig;
                afr[mt][0] = Ws[buf][r * BKP + c];
                afr[mt][1] = Ws[buf][(r + 8) * BKP + c];
                afr[mt][2] = Ws[buf][r * BKP + c + 4];
                afr[mt][3] = Ws[buf][(r + 8) * BKP + c + 4];
            }
#pragma unroll
            for (int nt = 0; nt < 4; nt++) {
                int col = wn * 32 + nt * 8 + gid;
                bfr[nt][0] = Xs[buf][(ks * 8 + tig) * BNP + col];
                bfr[nt][1] = Xs[buf][(ks * 8 + tig + 4) * BNP + col];
            }
#pragma unroll
            for (int mt = 0; mt < 4; mt++)
#pragma unroll
                for (int nt = 0; nt < 4; nt++)
                    mma_tf32(acc[mt][nt], afr[mt], bfr[nt]);
        }
    };

    const int NS = K >> 4;
    issue(0);
    issue(1);

    for (int s = 0; s < NS; s++) {
        if (s + 2 < NS) cp_wait<1>(); else cp_wait<0>();
        __syncthreads();
        compute(s);
        if (s + 2 < NS) issue(s + 2);
    }

    // --- epilogue ---
#pragma unroll
    for (int mt = 0; mt < 4; mt++) {
        int ocl0 = wm * 64 + mt * 16 + gid;
        float rs0 = 0.f, rs1 = 0.f, cb0 = 0.f, cb1 = 0.f;
        if (MODE == 1) {
            rs0 = rsum[oc0 + ocl0];  rs1 = rsum[oc0 + ocl0 + 8];
            cb0 = cbias[oc0 + ocl0]; cb1 = cbias[oc0 + ocl0 + 8];
        }
#pragma unroll
        for (int nt = 0; nt < 4; nt++) {
            int nl = wn * 32 + nt * 8 + tig * 2;
            size_t base0 = ((size_t)b * OC + oc0 + ocl0) * HW + n0 + nl;
            size_t base1 = ((size_t)b * OC + oc0 + ocl0 + 8) * HW + n0 + nl;
            float2 r0 = make_float2(acc[mt][nt][0], acc[mt][nt][1]);
            float2 r1 = make_float2(acc[mt][nt][2], acc[mt][nt][3]);
            if (MODE == 1) {
                float2 m2 = *(const float2*)&mu  [b * HW + n0 + nl];
                float2 d2 = *(const float2*)&rstd[b * HW + n0 + nl];
                r0.x = d2.x * (r0.x - m2.x * rs0) + cb0;
                r0.y = d2.y * (r0.y - m2.y * rs0) + cb0;
                r1.x = d2.x * (r1.x - m2.x * rs1) + cb1;
                r1.y = d2.y * (r1.y - m2.y * rs1) + cb1;
            }
            if (RESID) {
                float2 q0 = *(const float2*)&resid[base0];
                float2 q1 = *(const float2*)&resid[base1];
                r0.x += q0.x; r0.y += q0.y;
                r1.x += q1.x; r1.y += q1.y;
            }
            *(float2*)&out[base0] = r0;
            *(float2*)&out[base1] = r1;
        }
    }
}

// ---------------------------------------------------------------------------
// 2) Depthwise 3x3 conv, full-width 128x16 tiles, float4 I/O.
// ---------------------------------------------------------------------------
__global__ __launch_bounds__(256) void dwconv_k(const float* __restrict__ in,
                                                const float* __restrict__ wd,
                                                float* __restrict__ out,
                                                int CHN)
{
    __shared__ float t[18][136];
    int plane = blockIdx.y;
    int ch    = plane % CHN;
    size_t base = (size_t)plane * HW;
    int y0  = blockIdx.x * 16;
    int tid = threadIdx.x;

    if (tid < 36) t[tid >> 1][3 + (tid & 1) * 129] = 0.f;
#pragma unroll
    for (int i = tid; i < 576; i += 256) {
        int r = i >> 5, c4 = (i & 31) << 2;
        int gy = y0 - 1 + r;
        float4 v = make_float4(0.f, 0.f, 0.f, 0.f);
        if (gy >= 0 && gy < 128) v = *(const float4*)&in[base + gy * 128 + c4];
        *(float4*)&t[r][4 + c4] = v;
    }
    __syncthreads();

    float w[9];
#pragma unroll
    for (int j = 0; j < 9; j++) w[j] = wd[ch * 9 + j];

    int x4 = (tid & 31) << 2;
    int r0 = tid >> 5;
#pragma unroll
    for (int rr = 0; rr < 16; rr += 8) {
        int row = r0 + rr;
        float4 o = make_float4(0.f, 0.f, 0.f, 0.f);
#pragma unroll
        for (int dy = 0; dy < 3; dy++) {
            const float* tr = &t[row + dy][4 + x4];
            float m0 = tr[-1], m1 = tr[0], m2 = tr[1], m3 = tr[2], m4 = tr[3], m5 = tr[4];
            float a = w[dy * 3 + 0], bw = w[dy * 3 + 1], c = w[dy * 3 + 2];
            o.x = fmaf(a, m0, fmaf(bw, m1, fmaf(c, m2, o.x)));
            o.y = fmaf(a, m1, fmaf(bw, m2, fmaf(c, m3, o.y)));
            o.z = fmaf(a, m2, fmaf(bw, m3, fmaf(c, m4, o.z)));
            o.w = fmaf(a, m3, fmaf(bw, m4, fmaf(c, m5, o.w)));
        }
        *(float4*)&out[base + (y0 + row) * 128 + x4] = o;
    }
}

// ---------------------------------------------------------------------------
// 2b) GDFN: dwconv of x1/x2 + gelu gate, fused. in 512ch -> out 256ch.
// ---------------------------------------------------------------------------
__global__ __launch_bounds__(256) void dwgate_k(const float* __restrict__ in,
                                                const float* __restrict__ wd,
                                                float* __restrict__ out)
{
    __shared__ float t1[18][136];
    __shared__ float t2[18][136];
    int plane = blockIdx.y;
    int b  = plane >> 8, ch = plane & 255;
    size_t base1 = ((size_t)b * 512 + ch) * HW;
    size_t base2 = ((size_t)b * 512 + 256 + ch) * HW;
    size_t baseo = ((size_t)b * 256 + ch) * HW;
    int y0  = blockIdx.x * 16;
    int tid = threadIdx.x;

    if (tid < 36) {
        t1[tid >> 1][3 + (tid & 1) * 129] = 0.f;
        t2[tid >> 1][3 + (tid & 1) * 129] = 0.f;
    }
#pragma unroll
    for (int i = tid; i < 576; i += 256) {
        int r = i >> 5, c4 = (i & 31) << 2;
        int gy = y0 - 1 + r;
        float4 v1 = make_float4(0.f, 0.f, 0.f, 0.f);
        float4 v2 = make_float4(0.f, 0.f, 0.f, 0.f);
        if (gy >= 0 && gy < 128) {
            v1 = *(const float4*)&in[base1 + gy * 128 + c4];
            v2 = *(const float4*)&in[base2 + gy * 128 + c4];
        }
        *(float4*)&t1[r][4 + c4] = v1;
        *(float4*)&t2[r][4 + c4] = v2;
    }
    __syncthreads();

    float wA[9], wB[9];
#pragma unroll
    for (int j = 0; j < 9; j++) { wA[j] = wd[ch * 9 + j]; wB[j] = wd[(256 + ch) * 9 + j]; }

    int x4 = (tid & 31) << 2;
    int r0 = tid >> 5;
#pragma unroll
    for (int rr = 0; rr < 16; rr += 8) {
        int row = r0 + rr;
        float4 o1 = make_float4(0.f, 0.f, 0.f, 0.f);
        float4 o2 = make_float4(0.f, 0.f, 0.f, 0.f);
#pragma unroll
        for (int dy = 0; dy < 3; dy++) {
            {
                const float* tr = &t1[row + dy][4 + x4];
                float m0 = tr[-1], m1 = tr[0], m2 = tr[1], m3 = tr[2], m4 = tr[3], m5 = tr[4];
                float a = wA[dy * 3 + 0], bw = wA[dy * 3 + 1], c = wA[dy * 3 + 2];
                o1.x = fmaf(a, m0, fmaf(bw, m1, fmaf(c, m2, o1.x)));
                o1.y = fmaf(a, m1, fmaf(bw, m2, fmaf(c, m3, o1.y)));
                o1.z = fmaf(a, m2, fmaf(bw, m3, fmaf(c, m4, o1.z)));
                o1.w = fmaf(a, m3, fmaf(bw, m4, fmaf(c, m5, o1.w)));
            }
            {
                const float* tr = &t2[row + dy][4 + x4];
                float m0 = tr[-1], m1 = tr[0], m2 = tr[1], m3 = tr[2], m4 = tr[3], m5 = tr[4];
                float a = wB[dy * 3 + 0], bw = wB[dy * 3 + 1], c = wB[dy * 3 + 2];
                o2.x = fmaf(a, m0, fmaf(bw, m1, fmaf(c, m2, o2.x)));
                o2.y = fmaf(a, m1, fmaf(bw, m2, fmaf(c, m3, o2.y)));
                o2.z = fmaf(a, m2, fmaf(bw, m3, fmaf(c, m4, o2.z)));
                o2.w = fmaf(a, m3, fmaf(bw, m4, fmaf(c, m5, o2.w)));
            }
        }
        float4 g;
        g.x = gelu_exact(o1.x) * o2.x;
        g.y = gelu_exact(o1.y) * o2.y;
        g.z = gelu_exact(o1.z) * o2.z;
        g.w = gelu_exact(o1.w) * o2.w;
        *(float4*)&out[baseo + (y0 + row) * 128 + x4] = g;
    }
}

// ---------------------------------------------------------------------------
// 3) Attention logits (float4 loads) + fused sq-norm partials
// ---------------------------------------------------------------------------
__global__ __launch_bounds__(256) void attn_logits_k(const float* __restrict__ qkv)
{
    int seg = blockIdx.x;
    int bh  = blockIdx.y;
    int b = bh >> 3, h = bh & 7;
    const float* qb = qkv + ((size_t)b * 384 + h * DHEAD) * HW + seg * 128;
    const float* kb = qkv + ((size_t)b * 384 + 128 + h * DHEAD) * HW + seg * 128;

    __shared__ __align__(16) float qs[16][132];
    __shared__ __align__(16) float ks[16][132];

    int tid = threadIdx.x;
#pragma unroll
    for (int t = 0; t < 2; t++) {
        int idx = tid + t * 256;            // 512 float4 chunks: 16 rows x 32
        int row = idx >> 5, c4 = (idx & 31) << 2;
        *(float4*)&qs[row][c4] = *(const float4*)&qb[(size_t)row * HW + c4];
        *(float4*)&ks[row][c4] = *(const float4*)&kb[(size_t)row * HW + c4];
    }
    __syncthreads();

    int i = tid >> 4, j = tid & 15;
    bool diag = (i == j);
    const float4* q4 = (const float4*)&qs[i][0];
    const float4* k4 = (const float4*)&ks[j][0];
    float acc = 0.f, q2 = 0.f, k2 = 0.f;
#pragma unroll 8
    for (int n4 = 0; n4 < 32; n4++) {
        float4 a = q4[n4];
        float4 c = k4[n4];
        acc = fmaf(a.x, c.x, acc); acc = fmaf(a.y, c.y, acc);
        acc = fmaf(a.z, c.z, acc); acc = fmaf(a.w, c.w, acc);
        if (diag) {
            q2 = fmaf(a.x, a.x, q2); q2 = fmaf(a.y, a.y, q2);
            q2 = fmaf(a.z, a.z, q2); q2 = fmaf(a.w, a.w, q2);
            k2 = fmaf(c.x, c.x, k2); k2 = fmaf(c.y, c.y, k2);
            k2 = fmaf(c.z, c.z, k2); k2 = fmaf(c.w, c.w, k2);
        }
    }

    int slot = bh * ALOG_SEGS + seg;
    g_partS[(size_t)slot * 256 + tid] = acc;
    if (diag) {
        g_partQ2[slot * 16 + i] = q2;
        g_partK2[slot * 16 + i] = k2;
    }
}

// ---------------------------------------------------------------------------
// 4) Finalize: reduce segments, l2norm scale, temperature, softmax
// ---------------------------------------------------------------------------
__global__ __launch_bounds__(256) void attn_finalize_k(const float* __restrict__ temp)
{
    int bh = blockIdx.x;
    int h = bh & 7;
    int i = threadIdx.x >> 4, j = threadIdx.x & 15;

    float s = 0.f, q2 = 0.f, k2 = 0.f;
    for (int seg = 0; seg < ALOG_SEGS; seg++) {
        int slot = bh * ALOG_SEGS + seg;
        s  += g_partS [(size_t)slot * 256 + threadIdx.x];
        q2 += g_partQ2[slot * 16 + i];
        k2 += g_partK2[slot * 16 + j];
    }
    float rq = 1.f / fmaxf(sqrtf(q2), 1e-12f);
    float rk = 1.f / fmaxf(sqrtf(k2), 1e-12f);
    s = s * rq * rk * temp[h];

    float m = s;
    m = fmaxf(m, __shfl_xor_sync(0xffffffffu, m, 8, 16));
    m = fmaxf(m, __shfl_xor_sync(0xffffffffu, m, 4, 16));
    m = fmaxf(m, __shfl_xor_sync(0xffffffffu, m, 2, 16));
    m = fmaxf(m, __shfl_xor_sync(0xffffffffu, m, 1, 16));
    float e = expf(s - m);
    float sum = e;
    sum += __shfl_xor_sync(0xffffffffu, sum, 8, 16);
    sum += __shfl_xor_sync(0xffffffffu, sum, 4, 16);
    sum += __shfl_xor_sync(0xffffffffu, sum, 2, 16);
    sum += __shfl_xor_sync(0xffffffffu, sum, 1, 16);
    g_attn[bh * 256 + threadIdx.x] = e / sum;
}

// ---------------------------------------------------------------------------
// 5) Effective proj weights (tf32-rounded so GEMM can cp.async them raw)
// ---------------------------------------------------------------------------
__global__ __launch_bounds__(256) void weff_k(const float* __restrict__ proj_w)
{
    int b = blockIdx.x, h = blockIdx.y;
    __shared__ float at[16][16];
    __shared__ float pw[128][16];
    int tid = threadIdx.x;

    at[tid >> 4][tid & 15] = g_attn[(b * 8 + h) * 256 + tid];
#pragma unroll
    for (int t = 0; t < 8; t++) {
        int idx = tid + t * 256;
        int o = idx >> 4, i = idx & 15;
        pw[o][i] = proj_w[o * 128 + h * 16 + i];
    }
    __syncthreads();

#pragma unroll
    for (int t = 0; t < 8; t++) {
        int idx = tid + t * 256;
        int o = idx >> 4, e = idx & 15;
        float s = 0.f;
#pragma unroll
        for (int i = 0; i < 16; i++) s = fmaf(pw[o][i], at[i][e], s);
        g_Weff[((size_t)b * 128 + o) * 128 + h * 16 + e] = __uint_as_float(f2tf(s));
    }
}

// ---------------------------------------------------------------------------
// Launch
// ---------------------------------------------------------------------------
extern "C" void kernel_launch(void* const* d_in, const int* in_sizes, int n_in,
                              void* d_out, int out_size)
{
    const float* x      = (const float*)d_in[0];
    const float* ln1_w  = (const float*)d_in[1];
    const float* ln1_b  = (const float*)d_in[2];
    const float* temp   = (const float*)d_in[3];
    const float* qkv_pw = (const float*)d_in[4];
    const float* qkv_dw = (const float*)d_in[5];
    const float* proj_w = (const float*)d_in[6];
    const float* ln2_w  = (const float*)d_in[7];
    const float* ln2_b  = (const float*)d_in[8];
    const float* g1_w   = (const float*)d_in[9];
    const float* gd_w   = (const float*)d_in[10];
    const float* g2_w   = (const float*)d_in[11];
    float* out = (float*)d_out;

    float *bufA, *bufB, *WqP, *Wg1P, *Wg2P, *rs, *cb, *Weff, *mu, *rstd;
    cudaGetSymbolAddress((void**)&bufA, g_bufA);
    cudaGetSymbolAddress((void**)&bufB, g_bufB);
    cudaGetSymbolAddress((void**)&WqP,  g_WqP);
    cudaGetSymbolAddress((void**)&Wg1P, g_Wg1P);
    cudaGetSymbolAddress((void**)&Wg2P, g_Wg2P);
    cudaGetSymbolAddress((void**)&rs,   g_rs);
    cudaGetSymbolAddress((void**)&cb,   g_cb);
    cudaGetSymbolAddress((void**)&Weff, g_Weff);
    cudaGetSymbolAddress((void**)&mu,   g_mu);
    cudaGetSymbolAddress((void**)&rstd, g_rstd);

    dim3 b256(256);

    prep_w_k<<<128, b256>>>(qkv_pw, ln1_w, ln1_b, g1_w, ln2_w, ln2_b, g2_w);

    // --- MDTA ---
    ln_stats_k<<<dim3(16, BATCH), b256>>>(x, mu, rstd);
    gemm_tc<1, false><<<dim3(HW / BN, 384 / BM, BATCH), b256>>>(
        WqP, x, mu, rstd, rs, cb, nullptr, bufA, 384, 128, 128, 0);
    dwconv_k<<<dim3(8, BATCH * 384), b256>>>(bufA, qkv_dw, bufB, 384);
    attn_logits_k<<<dim3(ALOG_SEGS, 32), b256>>>(bufB);
    attn_finalize_k<<<32, b256>>>(temp);
    weff_k<<<dim3(4, 8), b256>>>(proj_w);
    gemm_tc<0, true><<<dim3(HW / BN, 1, BATCH), b256>>>(
        Weff, bufB + (size_t)256 * HW, nullptr, nullptr, nullptr, nullptr,
        x, out, 128, 128, 384, 128 * 128);

    // --- GDFN ---
    ln_stats_k<<<dim3(16, BATCH), b256>>>(out, mu, rstd);
    gemm_tc<1, false><<<dim3(HW / BN, 512 / BM, BATCH), b256>>>(
        Wg1P, out, mu, rstd, rs + 384, cb + 384, nullptr, bufA, 512, 128, 128, 0);
    dwgate_k<<<dim3(8, BATCH * 256), b256>>>(bufA, gd_w, bufB);
    gemm_tc<0, true><<<dim3(HW / BN, 1, BATCH), b256>>>(
        Wg2P, bufB, nullptr, nullptr, nullptr, nullptr,
        out, out, 128, 256, 256, 0);
}